// round 17
// baseline (speedup 1.0000x reference)
#include <cuda_runtime.h>
#include <cuda_bf16.h>
#include <cstdint>
#include <cstddef>

#define Bsz 128
#define Ssz 1024
#define Dsz 256
#define Hsz 256
#define G3  768

typedef unsigned long long ull;

// 402 MB scratch for precomputed input gates gx = x @ W_ih + b_ih
__device__ float g_gx[(size_t)Bsz * Ssz * G3];

__device__ __forceinline__ ull pk(float a, float b) {
    ull r;
    asm("mov.b64 %0, {%1, %2};" : "=l"(r) : "f"(a), "f"(b));
    return r;
}
__device__ __forceinline__ void fma2(ull& acc, ull a, ull b) {
    asm("fma.rn.f32x2 %0, %1, %2, %0;" : "+l"(acc) : "l"(a), "l"(b));
}

// Convert 8 fp32 -> 8 bf16 (hi part, or lo residual) packed as uint4
__device__ __forceinline__ uint4 to_bf16x8(float4 a, float4 b, bool lo) {
    float v[8] = {a.x, a.y, a.z, a.w, b.x, b.y, b.z, b.w};
    unsigned r[4];
#pragma unroll
    for (int e = 0; e < 4; e++) {
        float v0 = v[e * 2], v1 = v[e * 2 + 1];
        __nv_bfloat16 h0 = __float2bfloat16(v0);
        __nv_bfloat16 h1 = __float2bfloat16(v1);
        if (lo) {
            h0 = __float2bfloat16(v0 - __bfloat162float(h0));
            h1 = __float2bfloat16(v1 - __bfloat162float(h1));
        }
        r[e] = (unsigned)*reinterpret_cast<unsigned short*>(&h0) |
               ((unsigned)*reinterpret_cast<unsigned short*>(&h1) << 16);
    }
    return make_uint4(r[0], r[1], r[2], r[3]);
}

// ===========================================================================
// Kernel A: gx = X @ W_ih + b_ih via mma.sync bf16 (HMMA), 3-term split as
// K_eff=768 (panels hi*hi / hi*lo / lo*hi). SPLIT FUSED: loads fp32 X/W and
// converts to bf16 hi/lo at smem commit (no split kernels, no bf16 scratch).
// CTA 128x128, 8 warps of 64x32, K-step 32, double-buffered smem,
// fp32 accum, smem-staged coalesced epilogue.
// ===========================================================================
#define APAD 40
#define BPAD 136
#define AS_BUF (128 * APAD * 2)
#define BS_BUF (32 * BPAD * 2)
#define BS_BASE (2 * AS_BUF)
#define SMEM_GEMM (BS_BASE + 2 * BS_BUF)
#define EPAD 136

__global__ __launch_bounds__(256, 2) void gemm_gx_mma(
    const float* __restrict__ X, const float* __restrict__ W,
    const float* __restrict__ bias)
{
    extern __shared__ char smg[];
    const int tid  = threadIdx.x;
    const int lane = tid & 31;
    const int wid  = tid >> 5;
    const int brow = blockIdx.y * 128;
    const int bcol = blockIdx.x * 128;
    const int warp_m = (wid >> 2) * 64;
    const int warp_n = (wid & 3) * 32;

    float c[4][4][4];
#pragma unroll
    for (int tm = 0; tm < 4; tm++)
#pragma unroll
        for (int tn = 0; tn < 4; tn++)
#pragma unroll
            for (int r = 0; r < 4; r++) c[tm][tn][r] = 0.f;

    int arow[2], ak8[2], bkr[2], bn8[2];
#pragma unroll
    for (int ch = 0; ch < 2; ch++) {
        int id = tid + ch * 256;
        arow[ch] = id >> 2;
        ak8[ch]  = (id & 3) * 8;
        bkr[ch]  = id >> 4;
        bn8[ch]  = (id & 15) * 8;
    }

    uint32_t smB;
    asm("{ .reg .u64 t; cvta.to.shared.u64 t, %1; cvt.u32.u64 %0, t; }"
        : "=r"(smB) : "l"(smg));

    const uint32_t aLaneOff = (uint32_t)(((lane & 15) * APAD + (lane >> 4) * 8) * 2);
    const uint32_t bLaneOff = (uint32_t)(((((lane >> 3) & 1) * 8 + (lane & 7)) * BPAD
                                          + (lane >> 4) * 8) * 2);

    // prologue: load + convert iteration 0 (panel 0: hi/hi, k0 = 0)
    uint4 ra[2], rb[2];
#pragma unroll
    for (int ch = 0; ch < 2; ch++) {
        const float* ap = &X[(size_t)(brow + arow[ch]) * Dsz + ak8[ch]];
        const float* bp = &W[(size_t)bkr[ch] * G3 + bcol + bn8[ch]];
        ra[ch] = to_bf16x8(*reinterpret_cast<const float4*>(ap),
                           *reinterpret_cast<const float4*>(ap + 4), false);
        rb[ch] = to_bf16x8(*reinterpret_cast<const float4*>(bp),
                           *reinterpret_cast<const float4*>(bp + 4), false);
    }

#pragma unroll 1
    for (int it = 0; it < 24; it++) {
        const int buf = it & 1;
        __nv_bfloat16* As = reinterpret_cast<__nv_bfloat16*>(smg + buf * AS_BUF);
        __nv_bfloat16* Bs = reinterpret_cast<__nv_bfloat16*>(smg + BS_BASE + buf * BS_BUF);

        // commit staged (already converted) regs to smem[buf]
#pragma unroll
        for (int ch = 0; ch < 2; ch++) {
            *reinterpret_cast<uint4*>(&As[arow[ch] * APAD + ak8[ch]]) = ra[ch];
            *reinterpret_cast<uint4*>(&Bs[bkr[ch] * BPAD + bn8[ch]]) = rb[ch];
        }
        __syncthreads();

        // load + convert next iteration's tiles (fp32 -> bf16 hi/lo by panel)
        if (it + 1 < 24) {
            int itn = it + 1;
            int p   = itn >> 3;
            int k0  = (itn & 7) * 32;
            bool aLo = (p == 2);
            bool bLo = (p == 1);
#pragma unroll
            for (int ch = 0; ch < 2; ch++) {
                const float* ap = &X[(size_t)(brow + arow[ch]) * Dsz + k0 + ak8[ch]];
                const float* bp = &W[(size_t)(k0 + bkr[ch]) * G3 + bcol + bn8[ch]];
                ra[ch] = to_bf16x8(*reinterpret_cast<const float4*>(ap),
                                   *reinterpret_cast<const float4*>(ap + 4), aLo);
                rb[ch] = to_bf16x8(*reinterpret_cast<const float4*>(bp),
                                   *reinterpret_cast<const float4*>(bp + 4), bLo);
            }
        }

        // compute from smem[buf]
        const uint32_t asb = smB + (uint32_t)(buf * AS_BUF);
        const uint32_t bsb = smB + (uint32_t)(BS_BASE + buf * BS_BUF);
#pragma unroll
        for (int kh = 0; kh < 2; kh++) {
            uint32_t a[4][4];
#pragma unroll
            for (int tm = 0; tm < 4; tm++) {
                uint32_t addr = asb + aLaneOff +
                    (uint32_t)(((warp_m + tm * 16) * APAD + kh * 16) * 2);
                asm volatile(
                    "ldmatrix.sync.aligned.m8n8.x4.shared.b16 {%0,%1,%2,%3}, [%4];"
                    : "=r"(a[tm][0]), "=r"(a[tm][1]), "=r"(a[tm][2]), "=r"(a[tm][3])
                    : "r"(addr));
            }
            uint32_t b[4][2];
#pragma unroll
            for (int tnh = 0; tnh < 2; tnh++) {
                uint32_t addr = bsb + bLaneOff +
                    (uint32_t)((kh * 16 * BPAD + warp_n + tnh * 16) * 2);
                uint32_t r0, r1, r2, r3;
                asm volatile(
                    "ldmatrix.sync.aligned.m8n8.x4.trans.shared.b16 {%0,%1,%2,%3}, [%4];"
                    : "=r"(r0), "=r"(r1), "=r"(r2), "=r"(r3)
                    : "r"(addr));
                b[tnh * 2][0] = r0; b[tnh * 2][1] = r1;
                b[tnh * 2 + 1][0] = r2; b[tnh * 2 + 1][1] = r3;
            }
#pragma unroll
            for (int tm = 0; tm < 4; tm++)
#pragma unroll
                for (int tn = 0; tn < 4; tn++) {
                    asm volatile(
                        "mma.sync.aligned.m16n8k16.row.col.f32.bf16.bf16.f32 "
                        "{%0,%1,%2,%3}, {%4,%5,%6,%7}, {%8,%9}, {%0,%1,%2,%3};"
                        : "+f"(c[tm][tn][0]), "+f"(c[tm][tn][1]),
                          "+f"(c[tm][tn][2]), "+f"(c[tm][tn][3])
                        : "r"(a[tm][0]), "r"(a[tm][1]), "r"(a[tm][2]), "r"(a[tm][3]),
                          "r"(b[tn][0]), "r"(b[tn][1]));
                }
        }
    }

    // smem-staged epilogue: 2 rounds of 64 rows, coalesced float4 stores
    float* st = reinterpret_cast<float*>(smg);
#pragma unroll 1
    for (int rnd = 0; rnd < 2; rnd++) {
        __syncthreads();
        if ((wid >> 2) == rnd) {
            const int mb = lane >> 2;
            const int nb = (lane & 3) * 2;
#pragma unroll
            for (int tm = 0; tm < 4; tm++) {
                int ml = tm * 16 + mb;
#pragma unroll
                for (int tn = 0; tn < 4; tn++) {
                    int n0 = warp_n + tn * 8 + nb;
                    *reinterpret_cast<float2*>(&st[ml * EPAD + n0]) =
                        make_float2(c[tm][tn][0], c[tm][tn][1]);
                    *reinterpret_cast<float2*>(&st[(ml + 8) * EPAD + n0]) =
                        make_float2(c[tm][tn][2], c[tm][tn][3]);
                }
            }
        }
        __syncthreads();
        const int c4 = (tid & 31) * 4;
        float4 bv = *reinterpret_cast<const float4*>(&bias[bcol + c4]);
#pragma unroll
        for (int i = 0; i < 8; i++) {
            int row = i * 8 + (tid >> 5);
            float4 v = *reinterpret_cast<float4*>(&st[row * EPAD + c4]);
            v.x += bv.x; v.y += bv.y; v.z += bv.z; v.w += bv.w;
            *reinterpret_cast<float4*>(
                &g_gx[(size_t)(brow + rnd * 64 + row) * G3 + bcol + c4]) = v;
        }
    }
}

// ===========================================================================
// Kernel B: persistent GRU recurrence — EXACT R8/R13 configuration (1808us):
// bulk DSMEM h exchange, NKREG 20, TPB 256. Best-measured B; frozen.
// ===========================================================================
#define TPB_B 256
#define NKREG 20
#define NKSM  12

#define ULL_W     0
#define ULL_H     (8 * NKSM * 3 * 32)          // 9216
#define ULL_RED   (ULL_H + 2 * 256 * 4)        // 11264
#define ULL_STAGE (ULL_RED + 8 * 4 * 3 * 32)   // 14336
#define ULL_TOT   (ULL_STAGE + 2 * 256)        // 14848
#define SMEM_B_BYTES (ULL_TOT * 8 + 16)

__device__ __forceinline__ float sigmoidf_fast(float x) {
    return __fdividef(1.0f, 1.0f + __expf(-x));
}
__device__ __forceinline__ float tanhf_fast(float x) {
    x = fminf(fmaxf(x, -15.f), 15.f);
    float e = __expf(2.f * x);
    return __fdividef(e - 1.f, e + 1.f);
}

__device__ __forceinline__ void mbar_wait_parity(uint32_t mbar, uint32_t parity) {
    asm volatile(
        "{\n\t"
        ".reg .pred P;\n\t"
        "WAIT_%=:\n\t"
        "mbarrier.try_wait.parity.acquire.cluster.shared::cta.b64 P, [%0], %1, 0x989680;\n\t"
        "@P bra DONE_%=;\n\t"
        "bra WAIT_%=;\n\t"
        "DONE_%=:\n\t"
        "}"
        :: "r"(mbar), "r"(parity) : "memory");
}

__global__ void __cluster_dims__(4, 1, 1) __launch_bounds__(TPB_B, 1)
gru_rec_kernel(const float* __restrict__ mask,
               const float* __restrict__ Whh,
               const float* __restrict__ bhh,
               float* __restrict__ out)
{
    extern __shared__ ull smu[];
    ull* Ws2   = smu + ULL_W;
    ull* hb2   = smu + ULL_H;
    ull* red   = smu + ULL_RED;
    ull* stage = smu + ULL_STAGE;

    const int tid = threadIdx.x;
    uint32_t rank;
    asm("mov.u32 %0, %%cluster_ctarank;" : "=r"(rank));
    const int ci = (int)blockIdx.x >> 2;

    uint32_t sm_u32;
    asm("{ .reg .u64 t; cvta.to.shared.u64 t, %1; cvt.u32.u64 %0, t; }"
        : "=r"(sm_u32) : "l"(smu));
    const uint32_t hb_u32    = sm_u32 + ULL_H * 8;
    const uint32_t stage_u32 = sm_u32 + ULL_STAGE * 8;
    const uint32_t mbar_u32  = sm_u32 + ULL_TOT * 8;

    if (tid == 0) {
        asm volatile("mbarrier.init.shared.b64 [%0], 1;" :: "r"(mbar_u32) : "memory");
        asm volatile("mbarrier.init.shared.b64 [%0], 1;" :: "r"(mbar_u32 + 8) : "memory");
        asm volatile("mbarrier.arrive.expect_tx.shared.b64 _, [%0], 8192;"
                     :: "r"(mbar_u32) : "memory");
        asm volatile("mbarrier.arrive.expect_tx.shared.b64 _, [%0], 8192;"
                     :: "r"(mbar_u32 + 8) : "memory");
    }

    for (int idx = tid; idx < 8 * NKSM * 3 * 32; idx += TPB_B) {
        int jp_ = idx & 31;
        int g   = (idx >> 5) % 3;
        int kk  = (idx / 96) % NKSM;
        int kq_ = idx / (96 * NKSM);
        int k   = kq_ * 32 + NKREG + kk;
        int base = k * G3 + g * 256 + (int)rank * 64 + jp_ * 2;
        Ws2[idx] = pk(Whh[base], Whh[base + 1]);
    }
    for (int idx = tid; idx < 2 * 256 * 4; idx += TPB_B) hb2[idx] = 0ull;

    const int kq = tid >> 5;
    const int jp = tid & 31;
    const int k0 = kq * 32;
    const int jg0 = (int)rank * 64 + jp * 2;

    ull wr[NKREG], wz[NKREG], wn[NKREG];
#pragma unroll
    for (int kk = 0; kk < NKREG; kk++) {
        int k = k0 + kk;
        wr[kk] = pk(Whh[k * G3 + jg0],       Whh[k * G3 + jg0 + 1]);
        wz[kk] = pk(Whh[k * G3 + 256 + jg0], Whh[k * G3 + 256 + jg0 + 1]);
        wn[kk] = pk(Whh[k * G3 + 512 + jg0], Whh[k * G3 + 512 + jg0 + 1]);
    }

    const int je = tid & 63;
    const int be = tid >> 6;
    const int jge = (int)rank * 64 + je;
    const float bhr = bhh[jge];
    const float bhz = bhh[256 + jge];
    const float bhn = bhh[512 + jge];
    const int bbg = ci * 4 + be;
    const float* gx_p = g_gx + (size_t)bbg * Ssz * G3;
    const float* m_p  = mask + (size_t)bbg * Ssz;
    float* out_p = out + (size_t)bbg * Ssz * Hsz + jge;

    __syncthreads();
    asm volatile("barrier.cluster.arrive.aligned;" ::: "memory");
    asm volatile("barrier.cluster.wait.aligned;" ::: "memory");

    int ph0 = 0, ph1 = 0;

    for (int t = 0; t < Ssz; t++) {
        const float* gxt = gx_p + (size_t)t * G3;
        float gxr = __ldcs(gxt + jge);
        float gxz = __ldcs(gxt + 256 + jge);
        float gxn = __ldcs(gxt + 512 + jge);
        float mt  = __ldg(m_p + t);

        const int mi = t & 1;
        if (t > 0) {
            uint32_t mb = mbar_u32 + (uint32_t)(mi * 8);
            if (mi == 0) { mbar_wait_parity(mb, ph0); ph0 ^= 1; }
            else         { mbar_wait_parity(mb, ph1); ph1 ^= 1; }
            if (tid == 0 && t + 2 < Ssz)
                asm volatile("mbarrier.arrive.expect_tx.shared.b64 _, [%0], 8192;"
                             :: "r"(mb) : "memory");
        }

        float hold = reinterpret_cast<const float*>(
            &hb2[mi * 1024 + jge * 4 + be])[0];

        ull ar[4] = {0, 0, 0, 0}, az[4] = {0, 0, 0, 0}, an[4] = {0, 0, 0, 0};
        const ull* hK = hb2 + mi * 1024 + k0 * 4;

#pragma unroll
        for (int kk = 0; kk < NKREG; kk++) {
            ulonglong2 h01 = *reinterpret_cast<const ulonglong2*>(hK + kk * 4);
            ulonglong2 h23 = *reinterpret_cast<const ulonglong2*>(hK + kk * 4 + 2);
            ull hh[4] = {h01.x, h01.y, h23.x, h23.y};
#pragma unroll
            for (int b = 0; b < 4; b++) {
                fma2(ar[b], hh[b], wr[kk]);
                fma2(az[b], hh[b], wz[kk]);
                fma2(an[b], hh[b], wn[kk]);
            }
        }
#pragma unroll
        for (int kk2 = 0; kk2 < NKSM; kk2++) {
            const ull* wb = Ws2 + ((kq * NKSM + kk2) * 3) * 32 + jp;
            ull w_r = wb[0];
            ull w_z = wb[32];
            ull w_n = wb[64];
            int kk = NKREG + kk2;
            ulonglong2 h01 = *reinterpret_cast<const ulonglong2*>(hK + kk * 4);
            ulonglong2 h23 = *reinterpret_cast<const ulonglong2*>(hK + kk * 4 + 2);
            ull hh[4] = {h01.x, h01.y, h23.x, h23.y};
#pragma unroll
            for (int b = 0; b < 4; b++) {
                fma2(ar[b], hh[b], w_r);
                fma2(az[b], hh[b], w_z);
                fma2(an[b], hh[b], w_n);
            }
        }

        {
            ull* rb = red + kq * 384 + jp;
#pragma unroll
            for (int b = 0; b < 4; b++) {
                rb[b * 96]      = ar[b];
                rb[b * 96 + 32] = az[b];
                rb[b * 96 + 64] = an[b];
            }
        }
        __syncthreads();

        {
            float ghr = bhr, ghz = bhz, ghn = bhn;
            const float* redf = reinterpret_cast<const float*>(red);
            const int fb = be * 192 + je;
#pragma unroll
            for (int q = 0; q < 8; q++) {
                const float* rp = redf + q * 768 + fb;
                ghr += rp[0];
                ghz += rp[64];
                ghn += rp[128];
            }
            float r = sigmoidf_fast(gxr + ghr);
            float z = sigmoidf_fast(gxz + ghz);
            float n = tanhf_fast(fmaf(r, ghn, gxn));
            float hnew = fmaf(z, hold - n, n);
            float hout = fmaf(mt, hnew - hold, hold);
            out_p[(size_t)t * Hsz] = hout;

            stage[(t & 1) * 256 + je * 4 + be] = pk(hout, hout);
        }
        __syncthreads();

        if (t < Ssz - 1 && tid < 4) {
            asm volatile("fence.proxy.async.shared::cta;" ::: "memory");
            uint32_t src = stage_u32 + (uint32_t)((t & 1) * 256 * 8);
            uint32_t dst_local = hb_u32 +
                (uint32_t)((((t + 1) & 1) * 1024 + (int)rank * 256) * 8);
            uint32_t mb_local = mbar_u32 + (uint32_t)(((t + 1) & 1) * 8);
            uint32_t dst_r, mb_r;
            asm volatile("mapa.shared::cluster.u32 %0, %1, %2;"
                         : "=r"(dst_r) : "r"(dst_local), "r"(tid));
            asm volatile("mapa.shared::cluster.u32 %0, %1, %2;"
                         : "=r"(mb_r) : "r"(mb_local), "r"(tid));
            asm volatile(
                "cp.async.bulk.shared::cluster.shared::cta."
                "mbarrier::complete_tx::bytes [%0], [%1], %2, [%3];"
                :: "r"(dst_r), "r"(src), "r"(2048), "r"(mb_r) : "memory");
        }
    }
}

// ---------------------------------------------------------------------------
extern "C" void kernel_launch(void* const* d_in, const int* in_sizes, int n_in,
                              void* d_out, int out_size)
{
    (void)in_sizes; (void)n_in; (void)out_size;
    const float* x    = (const float*)d_in[0];
    const float* mask = (const float*)d_in[1];
    const float* Wih  = (const float*)d_in[2];
    const float* Whh  = (const float*)d_in[3];
    const float* bih  = (const float*)d_in[4];
    const float* bhh  = (const float*)d_in[5];
    float* out = (float*)d_out;

    cudaFuncSetAttribute(gru_rec_kernel,
                         cudaFuncAttributeMaxDynamicSharedMemorySize,
                         SMEM_B_BYTES);

    // gx GEMM on tensor cores, split fused in-kernel (no split kernels)
    dim3 gridA(G3 / 128, (Bsz * Ssz) / 128);   // 6 x 1024
    gemm_gx_mma<<<gridA, 256, SMEM_GEMM>>>(x, Wih, bih);

    // recurrence (R8-exact, best measured)
    gru_rec_kernel<<<Bsz, TPB_B, SMEM_B_BYTES>>>(mask, Whh, bhh, out);
}